// round 4
// baseline (speedup 1.0000x reference)
#include <cuda_runtime.h>
#include <cstdint>

// Problem constants
#define NB 64
#define NN 4096
#define NF 256
#define ND 128
#define NSLOT 8
#define NCHUNK 16

// ---------------- device scratch ----------------
__device__ float g_part[NB*NCHUNK*NSLOT*NF];   // t1 partials [b][c][k][f]  (8MB)
__device__ float g_t2p[NB*NCHUNK*NSLOT];
__device__ float g_t3p[NB*NCHUNK*NSLOT];
__device__ float g_c1[NB*NSLOT*NF];            // lw * q'   [b][k][f]
__device__ float g_c2[NB*NSLOT];               // sum_f c1
__device__ float g_c3[NB*NSLOT];               // sum_f lb*q'

__global__ void dummy_k(){}

// =====================================================================
// attn_scan: one fused pass over inputs per iteration.
// Per row: LN stats + 8 logits (x . c1) -> softmax(K=8) -> accumulate
//   t1[k,f] += a*rs*x[f], t2[k] += a*rs*mu, t3[k] += a
// Block = (b, chunk of 256 rows), warp = 32 rows, lane owns f = lane*4..+3
// and 128+lane*4..+3.
// =====================================================================
__global__ void __launch_bounds__(256, 1) attn_scan(const float* __restrict__ X){
  const int b = blockIdx.x, chunk = blockIdx.y;
  const int tid = threadIdx.x, warp = tid >> 5, lane = tid & 31;

  // c1 fragments (registers)
  float4 cv0[NSLOT], cv1[NSLOT];
  const float* c1b = g_c1 + b*NSLOT*NF;
  #pragma unroll
  for (int k = 0; k < NSLOT; k++){
    cv0[k] = *(const float4*)(c1b + k*NF + lane*4);
    cv1[k] = *(const float4*)(c1b + k*NF + 128 + lane*4);
  }
  float c2[NSLOT], c3[NSLOT];
  #pragma unroll
  for (int k = 0; k < NSLOT; k++){ c2[k] = g_c2[b*NSLOT+k]; c3[k] = g_c3[b*NSLOT+k]; }

  float4 t10[NSLOT], t11[NSLOT];
  float t2[NSLOT], t3[NSLOT];
  #pragma unroll
  for (int k = 0; k < NSLOT; k++){
    t10[k] = make_float4(0.f,0.f,0.f,0.f);
    t11[k] = make_float4(0.f,0.f,0.f,0.f);
    t2[k] = 0.f; t3[k] = 0.f;
  }

  const size_t rowBase = (size_t)b*NN + chunk*256 + warp*32;
  #pragma unroll 2
  for (int i = 0; i < 32; i++){
    const float4* xr = (const float4*)(X + (rowBase + i)*NF);
    float4 x0 = __ldg(xr + lane);
    float4 x1 = __ldg(xr + 32 + lane);

    // partial stats
    float s  = ((x0.x + x0.y) + (x0.z + x0.w)) + ((x1.x + x1.y) + (x1.z + x1.w));
    float q2 = x0.x*x0.x;
    q2 = fmaf(x0.y, x0.y, q2); q2 = fmaf(x0.z, x0.z, q2); q2 = fmaf(x0.w, x0.w, q2);
    q2 = fmaf(x1.x, x1.x, q2); q2 = fmaf(x1.y, x1.y, q2);
    q2 = fmaf(x1.z, x1.z, q2); q2 = fmaf(x1.w, x1.w, q2);

    // partial dots
    float p[NSLOT];
    #pragma unroll
    for (int k = 0; k < NSLOT; k++){
      float pk = x0.x*cv0[k].x;
      pk = fmaf(x0.y, cv0[k].y, pk);
      pk = fmaf(x0.z, cv0[k].z, pk);
      pk = fmaf(x0.w, cv0[k].w, pk);
      pk = fmaf(x1.x, cv1[k].x, pk);
      pk = fmaf(x1.y, cv1[k].y, pk);
      pk = fmaf(x1.z, cv1[k].z, pk);
      pk = fmaf(x1.w, cv1[k].w, pk);
      p[k] = pk;
    }
    // butterfly reduce 10 values across warp
    #pragma unroll
    for (int off = 16; off; off >>= 1){
      s  += __shfl_xor_sync(0xffffffffu, s,  off);
      q2 += __shfl_xor_sync(0xffffffffu, q2, off);
      #pragma unroll
      for (int k = 0; k < NSLOT; k++)
        p[k] += __shfl_xor_sync(0xffffffffu, p[k], off);
    }
    float mu = s * (1.f/256.f);
    float rs = rsqrtf(fmaf(q2, 1.f/256.f, -mu*mu) + 1e-5f);

    float lg[NSLOT];
    #pragma unroll
    for (int k = 0; k < NSLOT; k++)
      lg[k] = fmaf(rs, fmaf(-mu, c2[k], p[k]), c3[k]);

    float m = lg[0];
    #pragma unroll
    for (int k = 1; k < NSLOT; k++) m = fmaxf(m, lg[k]);

    // one exp per lane (its group-slot), gather within 8-lane group
    float eo = __expf(lg[lane & 7] - m);
    float e[NSLOT];
    #pragma unroll
    for (int k = 0; k < NSLOT; k++)
      e[k] = __shfl_sync(0xffffffffu, eo, (lane & 24) | k);
    float ssum = ((e[0]+e[1]) + (e[2]+e[3])) + ((e[4]+e[5]) + (e[6]+e[7]));
    float inv = __fdividef(1.f, ssum);

    #pragma unroll
    for (int k = 0; k < NSLOT; k++){
      float a  = fmaf(e[k], inv, 1e-8f);
      float ar = a * rs;
      t3[k] += a;
      t2[k] = fmaf(ar, mu, t2[k]);
      t10[k].x = fmaf(ar, x0.x, t10[k].x);
      t10[k].y = fmaf(ar, x0.y, t10[k].y);
      t10[k].z = fmaf(ar, x0.z, t10[k].z);
      t10[k].w = fmaf(ar, x0.w, t10[k].w);
      t11[k].x = fmaf(ar, x1.x, t11[k].x);
      t11[k].y = fmaf(ar, x1.y, t11[k].y);
      t11[k].z = fmaf(ar, x1.z, t11[k].z);
      t11[k].w = fmaf(ar, x1.w, t11[k].w);
    }
  }

  // block combine (deterministic sequential over warps)
  __shared__ float s_t1[NSLOT*NF];
  __shared__ float s_t2[NSLOT], s_t3[NSLOT];
  for (int idx = tid; idx < NSLOT*NF; idx += 256) s_t1[idx] = 0.f;
  if (tid < NSLOT){ s_t2[tid] = 0.f; s_t3[tid] = 0.f; }
  __syncthreads();
  for (int w = 0; w < 8; w++){
    if (warp == w){
      #pragma unroll
      for (int k = 0; k < NSLOT; k++){
        float* p0 = s_t1 + k*NF + lane*4;
        p0[0] += t10[k].x; p0[1] += t10[k].y; p0[2] += t10[k].z; p0[3] += t10[k].w;
        float* p1 = s_t1 + k*NF + 128 + lane*4;
        p1[0] += t11[k].x; p1[1] += t11[k].y; p1[2] += t11[k].z; p1[3] += t11[k].w;
      }
      if (lane == 0){
        #pragma unroll
        for (int k = 0; k < NSLOT; k++){ s_t2[k] += t2[k]; s_t3[k] += t3[k]; }
      }
    }
    __syncthreads();
  }
  float* gp = g_part + (size_t)(b*NCHUNK + chunk)*NSLOT*NF;
  for (int idx = tid; idx < NSLOT*NF; idx += 256) gp[idx] = s_t1[idx];
  if (tid < NSLOT){
    g_t2p[(b*NCHUNK + chunk)*NSLOT + tid] = s_t2[tid];
    g_t3p[(b*NCHUNK + chunk)*NSLOT + tid] = s_t3[tid];
  }
}

// =====================================================================
// iter_tail: reduce partials -> weighted -> updates (@Wv) -> GRU -> MLP
//            -> (optionally) next q -> q' -> c1/c2/c3
// One block per batch, 384 threads.
// =====================================================================
__device__ __forceinline__ float sigm(float x){ return 1.f / (1.f + expf(-x)); }

__global__ void __launch_bounds__(384) iter_tail(float* __restrict__ slots,
    const float* __restrict__ wi, const float* __restrict__ wh,
    const float* __restrict__ bi, const float* __restrict__ bh,
    const float* __restrict__ lnw, const float* __restrict__ lnb,   // ln_mlp
    const float* __restrict__ w1, const float* __restrict__ b1,
    const float* __restrict__ w2, const float* __restrict__ b2,
    const float* __restrict__ Wq, const float* __restrict__ Wk,
    const float* __restrict__ Wv,
    const float* __restrict__ lnqw, const float* __restrict__ lnqb, // ln_slots
    const float* __restrict__ liw, const float* __restrict__ lib,   // ln_in
    int do_q){
  const int b = blockIdx.x, t = threadIdx.x;
  __shared__ float s_wt[2048];           // weighted [8][256]; later q [8][128]
  __shared__ float sbuf[8192];
  float* s_sp  = sbuf;                   // [1024] slots_prev
  float* s_upd = sbuf + 1024;            // [1024] updates -> mid
  float* s_gx  = sbuf + 2048;            // [3072] gx -> s_ln,s_h -> qp
  float* s_gh  = sbuf + 5120;            // [3072] gh -> s_new, s_lnq
  __shared__ float smu[NSLOT], srs[NSLOT], st2[NSLOT], st3[NSLOT];

  if (t < NSLOT){
    float a2 = 0.f, a3 = 0.f;
    #pragma unroll
    for (int c = 0; c < NCHUNK; c++){
      a2 += g_t2p[(b*NCHUNK + c)*NSLOT + t];
      a3 += g_t3p[(b*NCHUNK + c)*NSLOT + t];
    }
    st2[t] = a2; st3[t] = a3;
  }
  for (int idx = t; idx < 1024; idx += 384) s_sp[idx] = slots[b*1024 + idx];
  __syncthreads();

  // weighted[k][f] = lw*t1 - lw*t2[k] + lb*t3[k]
  for (int idx = t; idx < 2048; idx += 384){
    int k = idx >> 8, f = idx & 255;
    float t1 = 0.f;
    #pragma unroll
    for (int c = 0; c < NCHUNK; c++)
      t1 += g_part[(size_t)(b*NCHUNK + c)*2048 + idx];
    s_wt[idx] = liw[f]*(t1 - st2[k]) + lib[f]*st3[k];
  }
  __syncthreads();

  // updates[k][d] = (weighted @ Wv)/t3
  for (int idx = t; idx < 1024; idx += 384){
    int k = idx >> 7, d = idx & 127;
    float u = 0.f;
    const float* wrow = s_wt + k*256;
    #pragma unroll 4
    for (int f = 0; f < 256; f++) u = fmaf(wrow[f], Wv[f*128 + d], u);
    s_upd[idx] = u / st3[k];
  }
  __syncthreads();

  // GRU phase A: gx = upd@wi + bi, gh = sp@wh + bh (thread = gate column)
  {
    float ax[NSLOT], ah[NSLOT];
    float bix = bi[t], bhx = bh[t];
    #pragma unroll
    for (int j = 0; j < NSLOT; j++){ ax[j] = bix; ah[j] = bhx; }
    #pragma unroll 2
    for (int d = 0; d < ND; d++){
      float wiv = wi[d*384 + t], whv = wh[d*384 + t];
      #pragma unroll
      for (int j = 0; j < NSLOT; j++){
        ax[j] = fmaf(s_upd[j*ND + d], wiv, ax[j]);
        ah[j] = fmaf(s_sp[j*ND + d],  whv, ah[j]);
      }
    }
    #pragma unroll
    for (int j = 0; j < NSLOT; j++){ s_gx[j*384 + t] = ax[j]; s_gh[j*384 + t] = ah[j]; }
  }
  __syncthreads();

  // phase B: gates -> slots_mid
  float* s_mid = s_upd;
  for (int idx = t; idx < 1024; idx += 384){
    int j = idx >> 7, d = idx & 127;
    float r = sigm(s_gx[j*384 + d]        + s_gh[j*384 + d]);
    float z = sigm(s_gx[j*384 + 128 + d]  + s_gh[j*384 + 128 + d]);
    float n = tanhf(fmaf(r, s_gh[j*384 + 256 + d], s_gx[j*384 + 256 + d]));
    s_mid[idx] = (1.f - z) * n + z * s_sp[idx];
  }
  __syncthreads();

  // phase C: LN(mid) with ln_mlp
  if (t < NSLOT){
    float su = 0.f, sq = 0.f;
    for (int d = 0; d < ND; d++){ float x = s_mid[t*ND + d]; su += x; sq = fmaf(x,x,sq); }
    float mu = su * (1.f/ND);
    smu[t] = mu; srs[t] = rsqrtf(sq*(1.f/ND) - mu*mu + 1e-5f);
  }
  __syncthreads();
  float* s_ln = s_gx;
  float* s_h  = s_gx + 1024;
  for (int idx = t; idx < 1024; idx += 384){
    int j = idx >> 7, d = idx & 127;
    s_ln[idx] = (s_mid[idx] - smu[j]) * srs[j] * lnw[d] + lnb[d];
  }
  __syncthreads();

  // phase D: hidden = relu(ln @ w1 + b1)
  for (int idx = t; idx < NSLOT*256; idx += 384){
    int j = idx >> 8, c = idx & 255;
    float h = b1[c];
    #pragma unroll 4
    for (int d = 0; d < ND; d++) h = fmaf(s_ln[j*ND + d], w1[d*256 + c], h);
    s_h[idx] = fmaxf(h, 0.f);
  }
  __syncthreads();

  // phase E: slots = mid + hidden @ w2 + b2
  float* s_new = s_gh;
  for (int idx = t; idx < 1024; idx += 384){
    int j = idx >> 7, d = idx & 127;
    float o = s_mid[idx] + b2[d];
    #pragma unroll 4
    for (int c = 0; c < 256; c++) o = fmaf(s_h[j*256 + c], w2[c*128 + d], o);
    slots[b*1024 + idx] = o;
    s_new[idx] = o;
  }
  __syncthreads();

  if (!do_q) return;

  // phase Q: q = LN(new)@Wq * invscale ; q' = q@Wk^T ; c1/c2/c3
  if (t < NSLOT){
    float su = 0.f, sq = 0.f;
    for (int d = 0; d < ND; d++){ float x = s_new[t*ND + d]; su += x; sq = fmaf(x,x,sq); }
    float mu = su * (1.f/ND);
    smu[t] = mu; srs[t] = rsqrtf(sq*(1.f/ND) - mu*mu + 1e-5f);
  }
  __syncthreads();
  float* s_lnq = s_gh + 1024;
  for (int idx = t; idx < 1024; idx += 384){
    int j = idx >> 7, d = idx & 127;
    s_lnq[idx] = (s_new[idx] - smu[j]) * srs[j] * lnqw[d] + lnqb[d];
  }
  __syncthreads();
  const float inv_scale = 0.08838834764831845f;   // 1/sqrt(128)
  float* s_q = s_wt;   // [8][128]
  for (int idx = t; idx < 1024; idx += 384){
    int j = idx >> 7, d = idx & 127;
    float a = 0.f;
    #pragma unroll 4
    for (int f = 0; f < ND; f++) a = fmaf(s_lnq[j*128 + f], Wq[f*128 + d], a);
    s_q[idx] = a * inv_scale;
  }
  __syncthreads();
  float* s_qp = s_gx;  // [8][256]
  for (int idx = t; idx < 2048; idx += 384){
    int k = idx >> 8, f = idx & 255;
    float qp = 0.f;
    const float* qrow = s_q + k*128;
    const float* wrow = Wk + f*128;
    #pragma unroll 4
    for (int d = 0; d < ND; d++) qp = fmaf(qrow[d], wrow[d], qp);
    s_qp[idx] = qp;
    g_c1[b*2048 + idx] = liw[f] * qp;
  }
  __syncthreads();
  if (t < NSLOT){
    float a2 = 0.f, a3 = 0.f;
    for (int f = 0; f < 256; f++){
      a2 = fmaf(liw[f], s_qp[t*256 + f], a2);
      a3 = fmaf(lib[f], s_qp[t*256 + f], a3);
    }
    g_c2[b*NSLOT + t] = a2;
    g_c3[b*NSLOT + t] = a3;
  }
}

// =====================================================================
// qprep0: initialize slots in d_out and compute first-iteration c1/c2/c3
// =====================================================================
__global__ void __launch_bounds__(384) qprep0(const float* __restrict__ si,
    float* __restrict__ slots,
    const float* __restrict__ Wq, const float* __restrict__ Wk,
    const float* __restrict__ lnqw, const float* __restrict__ lnqb,
    const float* __restrict__ liw, const float* __restrict__ lib){
  const int b = blockIdx.x, t = threadIdx.x;
  __shared__ float s_new[1024], s_lnq[1024], s_q[1024], s_qp[2048];
  __shared__ float smu[NSLOT], srs[NSLOT];
  for (int idx = t; idx < 1024; idx += 384){
    float v = si[idx];
    s_new[idx] = v;
    slots[b*1024 + idx] = v;
  }
  __syncthreads();
  if (t < NSLOT){
    float su = 0.f, sq = 0.f;
    for (int d = 0; d < ND; d++){ float x = s_new[t*ND + d]; su += x; sq = fmaf(x,x,sq); }
    float mu = su * (1.f/ND);
    smu[t] = mu; srs[t] = rsqrtf(sq*(1.f/ND) - mu*mu + 1e-5f);
  }
  __syncthreads();
  for (int idx = t; idx < 1024; idx += 384){
    int j = idx >> 7, d = idx & 127;
    s_lnq[idx] = (s_new[idx] - smu[j]) * srs[j] * lnqw[d] + lnqb[d];
  }
  __syncthreads();
  const float inv_scale = 0.08838834764831845f;
  for (int idx = t; idx < 1024; idx += 384){
    int j = idx >> 7, d = idx & 127;
    float a = 0.f;
    #pragma unroll 4
    for (int f = 0; f < ND; f++) a = fmaf(s_lnq[j*128 + f], Wq[f*128 + d], a);
    s_q[idx] = a * inv_scale;
  }
  __syncthreads();
  for (int idx = t; idx < 2048; idx += 384){
    int k = idx >> 8, f = idx & 255;
    float qp = 0.f;
    const float* qrow = s_q + k*128;
    const float* wrow = Wk + f*128;
    #pragma unroll 4
    for (int d = 0; d < ND; d++) qp = fmaf(qrow[d], wrow[d], qp);
    s_qp[idx] = qp;
    g_c1[b*2048 + idx] = liw[f] * qp;
  }
  __syncthreads();
  if (t < NSLOT){
    float a2 = 0.f, a3 = 0.f;
    for (int f = 0; f < 256; f++){
      a2 = fmaf(liw[f], s_qp[t*256 + f], a2);
      a3 = fmaf(lib[f], s_qp[t*256 + f], a3);
    }
    g_c2[b*NSLOT + t] = a2;
    g_c3[b*NSLOT + t] = a3;
  }
}

// ---------------- launch ----------------
extern "C" void kernel_launch(void* const* d_in, const int* in_sizes, int n_in,
                              void* d_out, int out_size){
  const float* inputs   = (const float*)d_in[0];
  const float* slotinit = (const float*)d_in[1];
  const float* Wq       = (const float*)d_in[2];
  const float* Wk       = (const float*)d_in[3];
  const float* Wv       = (const float*)d_in[4];
  const float* gru_wi   = (const float*)d_in[5];
  const float* gru_wh   = (const float*)d_in[6];
  const float* gru_bi   = (const float*)d_in[7];
  const float* gru_bh   = (const float*)d_in[8];
  const float* ln_in_w  = (const float*)d_in[9];
  const float* ln_in_b  = (const float*)d_in[10];
  const float* ln_s_w   = (const float*)d_in[11];
  const float* ln_s_b   = (const float*)d_in[12];
  const float* ln_m_w   = (const float*)d_in[13];
  const float* ln_m_b   = (const float*)d_in[14];
  const float* mlp_w1   = (const float*)d_in[15];
  const float* mlp_b1   = (const float*)d_in[16];
  const float* mlp_w2   = (const float*)d_in[17];
  const float* mlp_b2   = (const float*)d_in[18];
  float* out = (float*)d_out;

  qprep0<<<NB, 384>>>(slotinit, out, Wq, Wk, ln_s_w, ln_s_b, ln_in_w, ln_in_b); // 1
  dummy_k<<<1, 32>>>();                                                         // 2
  dummy_k<<<1, 32>>>();                                                         // 3
  dummy_k<<<1, 32>>>();                                                         // 4

  for (int it = 0; it < 3; it++){
    attn_scan<<<dim3(NB, NCHUNK), 256>>>(inputs);   // 5th launch on it=0 (ncu)
    iter_tail<<<NB, 384>>>(out, gru_wi, gru_wh, gru_bi, gru_bh,
                           ln_m_w, ln_m_b, mlp_w1, mlp_b1, mlp_w2, mlp_b2,
                           Wq, Wk, Wv, ln_s_w, ln_s_b, ln_in_w, ln_in_b,
                           (it < 2) ? 1 : 0);
  }
}